// round 1
// baseline (speedup 1.0000x reference)
#include <cuda_runtime.h>
#include <math.h>

#define N_ITEMS 200000
#define N_USERS 100000
#define N_INTER 2000000
#define GCN 64
#define HID 256
#define TOW 128

// ---------------- scratch (static device globals; no runtime alloc) ----------
__device__ float g_item_emb[(size_t)N_ITEMS * TOW];   // 102.4 MB
__device__ float g_H[(size_t)N_ITEMS * HID];          // 204.8 MB (reused by user tower)
__device__ float g_fused[(size_t)N_USERS * (GCN + TOW)]; // 76.8 MB
__device__ int   g_start[N_USERS];
__device__ int   g_end[N_USERS];

// ---------------------------------------------------------------------------
// Generic fused layer:  Y = post( X @ W + b ),  X = concat(X1[k1], X2[K-k1])
//   - W (K x N, row-major) cached in SMEM once per CTA (persistent CTAs,
//     grid-stride over 16-row tiles)
//   - 256 threads, per-thread register tile 4 rows x (N/64) cols
//   - RELU: clamp + plain store.  L2N (N must be 128): stage to smem,
//     per-row warp reduction, scale, store.
// ---------------------------------------------------------------------------
template <int K, int N, bool RELU, bool L2N>
__global__ void __launch_bounds__(256, 1)
gemm_kernel(const float* __restrict__ X1, int k1,
            const float* __restrict__ X2,
            const float* __restrict__ W,
            const float* __restrict__ bias,
            float* __restrict__ Y, int M)
{
    static_assert(!L2N || N == 128, "L2 norm path assumes N==128");
    extern __shared__ float sm[];
    float* Ws = sm;                 // K*N
    float* Xs = sm + K * N;         // 16*K
    float* Os = Xs + 16 * K;        // 16*128 (only used when L2N)

    const int tid = threadIdx.x;

    // Load weights once per CTA.
    for (int i = tid; i < K * N; i += 256) Ws[i] = W[i];

    const int ty = tid >> 6;        // 0..3  (row group)
    const int tx = tid & 63;        // 0..63 (col lane)
    constexpr int RN = N / 64;      // 4 (N=256) or 2 (N=128)

    float breg[RN];
#pragma unroll
    for (int j = 0; j < RN; ++j) breg[j] = bias[tx + 64 * j];

    const int ntiles = (M + 15) >> 4;
    for (int tile = blockIdx.x; tile < ntiles; tile += gridDim.x) {
        const int row0 = tile << 4;
        __syncthreads();   // protect Xs/Os from previous-iteration readers (and W load, 1st iter)

        // Stage X tile [16 x K] (with concat + tail guard)
        for (int i = tid; i < 16 * K; i += 256) {
            int r = i / K;
            int c = i - r * K;
            int gr = row0 + r;
            float v = 0.f;
            if (gr < M)
                v = (c < k1) ? X1[gr * k1 + c]
                             : X2[gr * (K - k1) + (c - k1)];
            Xs[i] = v;
        }
        __syncthreads();

        float acc[4][RN];
#pragma unroll
        for (int i = 0; i < 4; ++i)
#pragma unroll
            for (int j = 0; j < RN; ++j) acc[i][j] = breg[j];

#pragma unroll 8
        for (int k = 0; k < K; ++k) {
            float a[4];
#pragma unroll
            for (int i = 0; i < 4; ++i) a[i] = Xs[(ty + 4 * i) * K + k];  // warp-broadcast
#pragma unroll
            for (int j = 0; j < RN; ++j) {
                float w = Ws[k * N + tx + 64 * j];                        // conflict-free
#pragma unroll
                for (int i = 0; i < 4; ++i) acc[i][j] = fmaf(a[i], w, acc[i][j]);
            }
        }

        if (RELU) {
#pragma unroll
            for (int i = 0; i < 4; ++i)
#pragma unroll
                for (int j = 0; j < RN; ++j) acc[i][j] = fmaxf(acc[i][j], 0.f);
        }

        if (!L2N) {
#pragma unroll
            for (int i = 0; i < 4; ++i) {
                int gr = row0 + ty + 4 * i;
                if (gr < M) {
#pragma unroll
                    for (int j = 0; j < RN; ++j)
                        Y[(size_t)gr * N + tx + 64 * j] = acc[i][j];
                }
            }
        } else {
            // stage, per-row L2 normalize, store
#pragma unroll
            for (int i = 0; i < 4; ++i)
#pragma unroll
                for (int j = 0; j < RN; ++j)
                    Os[(ty + 4 * i) * 128 + tx + 64 * j] = acc[i][j];
            __syncthreads();

            const int warp = tid >> 5;
            const int lane = tid & 31;
#pragma unroll
            for (int rr = 0; rr < 2; ++rr) {
                int r = warp * 2 + rr;     // 8 warps x 2 rows = 16 rows
                float v[4];
#pragma unroll
                for (int c = 0; c < 4; ++c) v[c] = Os[r * 128 + lane + 32 * c];
                float s = v[0] * v[0] + v[1] * v[1] + v[2] * v[2] + v[3] * v[3];
#pragma unroll
                for (int o = 16; o > 0; o >>= 1) s += __shfl_xor_sync(0xffffffffu, s, o);
                float scale = 1.0f / fmaxf(sqrtf(s), 1e-12f);
                int gr = row0 + r;
                if (gr < M) {
#pragma unroll
                    for (int c = 0; c < 4; ++c)
                        Y[(size_t)gr * 128 + lane + 32 * c] = v[c] * scale;
                }
            }
        }
    }
}

// ---------------------------------------------------------------------------
// Segment boundaries from sorted seg_ids (users with no interactions -> [0,0))
// ---------------------------------------------------------------------------
__global__ void bounds_init_kernel(int* __restrict__ s, int* __restrict__ e, int n)
{
    int i = blockIdx.x * blockDim.x + threadIdx.x;
    if (i < n) { s[i] = 0; e[i] = 0; }
}

__global__ void bounds_kernel(const int* __restrict__ seg, int n,
                              int* __restrict__ s, int* __restrict__ e)
{
    int i = blockIdx.x * blockDim.x + threadIdx.x;
    if (i >= n) return;
    int id = seg[i];
    if (i == 0 || seg[i - 1] != id) s[id] = i;
    if (i == n - 1 || seg[i + 1] != id) e[id] = i + 1;
}

// ---------------------------------------------------------------------------
// One warp per user: fused[u] = concat(gcn_user_emb[users[u]], mean(item_emb rows))
// float4 lanes: 32 lanes x 16B = one 128-float row per load step.
// ---------------------------------------------------------------------------
__global__ void hist_kernel(const float* __restrict__ item_emb,
                            const int* __restrict__ item_idx,
                            const int* __restrict__ sa,
                            const int* __restrict__ ea,
                            const float* __restrict__ gue,
                            const int* __restrict__ users,
                            float* __restrict__ fused, int n_users)
{
    int w = (blockIdx.x * blockDim.x + threadIdx.x) >> 5;
    int lane = threadIdx.x & 31;
    if (w >= n_users) return;

    int uu = users[w];

    // gcn part (64 floats = 16 float4)
    if (lane < 16) {
        float4 g = reinterpret_cast<const float4*>(gue + (size_t)uu * GCN)[lane];
        reinterpret_cast<float4*>(fused + (size_t)w * (GCN + TOW))[lane] = g;
    }

    int s = sa[uu], e = ea[uu];
    const float4* emb4 = reinterpret_cast<const float4*>(item_emb);

    float4 acc = make_float4(0.f, 0.f, 0.f, 0.f);
    int j = s;
    for (; j + 4 <= e; j += 4) {
        int i0 = item_idx[j], i1 = item_idx[j + 1], i2 = item_idx[j + 2], i3 = item_idx[j + 3];
        float4 v0 = emb4[(size_t)i0 * 32 + lane];
        float4 v1 = emb4[(size_t)i1 * 32 + lane];
        float4 v2 = emb4[(size_t)i2 * 32 + lane];
        float4 v3 = emb4[(size_t)i3 * 32 + lane];
        acc.x += (v0.x + v1.x) + (v2.x + v3.x);
        acc.y += (v0.y + v1.y) + (v2.y + v3.y);
        acc.z += (v0.z + v1.z) + (v2.z + v3.z);
        acc.w += (v0.w + v1.w) + (v2.w + v3.w);
    }
    for (; j < e; ++j) {
        int it = item_idx[j];
        float4 v = emb4[(size_t)it * 32 + lane];
        acc.x += v.x; acc.y += v.y; acc.z += v.z; acc.w += v.w;
    }
    float inv = 1.0f / fmaxf((float)(e - s), 1.0f);
    float4 m = make_float4(acc.x * inv, acc.y * inv, acc.z * inv, acc.w * inv);
    reinterpret_cast<float4*>(fused + (size_t)w * (GCN + TOW) + GCN)[lane] = m;
}

// ---------------------------------------------------------------------------
extern "C" void kernel_launch(void* const* d_in, const int* in_sizes, int n_in,
                              void* d_out, int out_size)
{
    const float* item_feat    = (const float*)d_in[0];   // [200000, 2]
    const float* gcn_item_emb = (const float*)d_in[1];   // [200000, 64]
    const float* gcn_user_emb = (const float*)d_in[2];   // [100000, 64]
    const float* Wi1 = (const float*)d_in[3];            // [66, 256]
    const float* bi1 = (const float*)d_in[4];            // [256]
    const float* Wi2 = (const float*)d_in[5];            // [256, 128]
    const float* bi2 = (const float*)d_in[6];            // [128]
    const float* Wu1 = (const float*)d_in[7];            // [192, 256]
    const float* bu1 = (const float*)d_in[8];            // [256]
    const float* Wu2 = (const float*)d_in[9];            // [256, 128]
    const float* bu2 = (const float*)d_in[10];           // [128]
    const int* item_idx = (const int*)d_in[11];          // [2M]
    const int* seg_ids  = (const int*)d_in[12];          // [2M] sorted
    const int* users    = (const int*)d_in[13];          // [100000]
    float* out = (float*)d_out;                          // [100000, 128]

    float *item_emb, *H, *fused;
    int *st, *en;
    cudaGetSymbolAddress((void**)&item_emb, g_item_emb);
    cudaGetSymbolAddress((void**)&H, g_H);
    cudaGetSymbolAddress((void**)&fused, g_fused);
    cudaGetSymbolAddress((void**)&st, g_start);
    cudaGetSymbolAddress((void**)&en, g_end);

    // dynamic smem sizes per instantiation
    const int smem_i1 = (66 * 256 + 16 * 66) * 4;                 // 71808
    const int smem_l2 = (256 * 128 + 16 * 256 + 16 * 128) * 4;    // 155648
    const int smem_u1 = (192 * 256 + 16 * 192) * 4;               // 208896

    cudaFuncSetAttribute((const void*)gemm_kernel<66, 256, true, false>,
                         cudaFuncAttributeMaxDynamicSharedMemorySize, smem_i1);
    cudaFuncSetAttribute((const void*)gemm_kernel<256, 128, false, true>,
                         cudaFuncAttributeMaxDynamicSharedMemorySize, smem_l2);
    cudaFuncSetAttribute((const void*)gemm_kernel<192, 256, true, false>,
                         cudaFuncAttributeMaxDynamicSharedMemorySize, smem_u1);

    const int GRID = 152;   // persistent CTAs, 1 per SM (GB300 has 152 SMs)

    // 1) item tower layer 1: H = relu(concat(item_feat, gcn_item_emb) @ Wi1 + bi1)
    gemm_kernel<66, 256, true, false><<<GRID, 256, smem_i1>>>(
        item_feat, 2, gcn_item_emb, Wi1, bi1, H, N_ITEMS);

    // 2) item tower layer 2 + L2 norm: item_emb
    gemm_kernel<256, 128, false, true><<<GRID, 256, smem_l2>>>(
        H, 256, H, Wi2, bi2, item_emb, N_ITEMS);

    // 3) segment boundaries (independent of 1-2, tiny)
    bounds_init_kernel<<<(N_USERS + 255) / 256, 256>>>(st, en, N_USERS);
    bounds_kernel<<<(N_INTER + 255) / 256, 256>>>(seg_ids, N_INTER, st, en);

    // 4) ragged gather + mean -> fused = [gcn_user_emb[users] | hist]
    hist_kernel<<<(N_USERS * 32 + 255) / 256, 256>>>(
        item_emb, item_idx, st, en, gcn_user_emb, users, fused, N_USERS);

    // 5) user tower layer 1
    gemm_kernel<192, 256, true, false><<<GRID, 256, smem_u1>>>(
        fused, 192, fused, Wu1, bu1, H, N_USERS);

    // 6) user tower layer 2 + L2 norm -> output
    gemm_kernel<256, 128, false, true><<<GRID, 256, smem_l2>>>(
        H, 256, H, Wu2, bu2, out, N_USERS);
}

// round 2
// speedup vs baseline: 1.0723x; 1.0723x over previous
#include <cuda_runtime.h>
#include <math.h>

#define N_ITEMS 200000
#define N_USERS 100000
#define N_INTER 2000000
#define GCN 64
#define HID 256
#define TOW 128

typedef unsigned long long u64;

// packed dual-FMA: (d.lo,d.hi) += (a.lo*b.lo, a.hi*b.hi)
#define FMA2(d, a, b) \
    asm("fma.rn.f32x2 %0, %1, %2, %0;" : "+l"(d) : "l"(a), "l"(b))

#define UNPACK2(lo, hi, p) \
    asm("mov.b64 {%0, %1}, %2;" : "=f"(lo), "=f"(hi) : "l"(p))

// ---------------- scratch (static device globals; no runtime alloc) ----------
__device__ float g_item_emb[(size_t)N_ITEMS * TOW];      // 102.4 MB
__device__ float g_H[(size_t)N_ITEMS * HID];             // 204.8 MB (reused by user tower)
__device__ float g_fused[(size_t)N_USERS * (GCN + TOW)]; // 76.8 MB
__device__ int   g_start[N_USERS];
__device__ int   g_end[N_USERS];

// padded K stride: multiple of 4 words AND ≡4 (mod 8) so 8-lane LDS.128 phases
// are bank-conflict-free (stride*4 words per lane covers all 32 banks).
template <int K> struct PadK {
    static constexpr int a = (K + 3) & ~3;
    static constexpr int value = (a % 8 == 4) ? a : a + 4;
};

// ---------------------------------------------------------------------------
// Fused layer: Y = post( X @ W + b ),  X = concat(X1[:k1], X2[:K-k1])
//  - W transposed into SMEM as Wt[N][K4] once per CTA (persistent CTAs)
//  - 256 threads = 4 row-groups x 64 col-lanes
//  - per-thread register tile: R rows x C cols, accumulated as f32x2 packed
//    along k (k, k+1) -> both operands naturally packed from LDS.128
//  - RELU: bias+relu+store.  L2N (N==128): per-row cross-warp L2 normalize.
// ---------------------------------------------------------------------------
template <int K, int N, bool RELU, bool L2N>
__global__ void __launch_bounds__(256, 1)
gemm_kernel(const float* __restrict__ X1, int k1,
            const float* __restrict__ X2,
            const float* __restrict__ W,
            const float* __restrict__ bias,
            float* __restrict__ Y, int M)
{
    constexpr int K4 = PadK<K>::value;
    constexpr int C  = N / 64;             // cols per thread (2 or 4)
    constexpr int R  = 32 / C;             // rows per thread (16 or 8)
    constexpr int TR = 4 * R;              // tile rows (64 or 32)
    constexpr int NG = K4 / 4;             // 4-k groups

    extern __shared__ float sm[];
    float* Ws = sm;                        // [N][K4] transposed weights
    float* Xs = sm + (size_t)N * K4;       // [TR][K4]
    float* Sr = Xs + (size_t)TR * K4;      // [8][R] row ssq partials (L2N)

    const int tid = threadIdx.x;
    const int ty = tid >> 6;               // 0..3
    const int tx = tid & 63;               // 0..63
    const int warp = tid >> 5;
    const int lane = tid & 31;

    // Stage transposed weights once (strided global reads -> coalesced STS).
    for (int i = tid; i < N * K4; i += 256) {
        int n = i / K4, k = i - n * K4;
        Ws[i] = (k < K) ? W[k * N + n] : 0.f;
    }

    float breg[C];
#pragma unroll
    for (int j = 0; j < C; ++j) breg[j] = bias[tx + 64 * j];

    const ulonglong2* wp[C];
#pragma unroll
    for (int j = 0; j < C; ++j)
        wp[j] = reinterpret_cast<const ulonglong2*>(Ws + (size_t)(tx + 64 * j) * K4);
    const ulonglong2* xp[R];
#pragma unroll
    for (int i = 0; i < R; ++i)
        xp[i] = reinterpret_cast<const ulonglong2*>(Xs + (size_t)(ty + 4 * i) * K4);

    const int ntiles = (M + TR - 1) / TR;
    for (int tile = blockIdx.x; tile < ntiles; tile += gridDim.x) {
        const int row0 = tile * TR;
        __syncthreads();   // protect Xs/Sr from previous iteration (and W load, 1st)

        // Stage X tile [TR x K4] with concat, tail guard, zero pad.
        for (int i = tid; i < TR * K4; i += 256) {
            int r = i / K4, c = i - r * K4;
            int gr = row0 + r;
            float v = 0.f;
            if (gr < M && c < K)
                v = (c < k1) ? X1[(size_t)gr * k1 + c]
                             : X2[(size_t)gr * (K - k1) + (c - k1)];
            Xs[i] = v;
        }
        __syncthreads();

        u64 acc[R][C];
#pragma unroll
        for (int i = 0; i < R; ++i)
#pragma unroll
            for (int j = 0; j < C; ++j) acc[i][j] = 0ull;

#pragma unroll 2
        for (int g = 0; g < NG; ++g) {
            ulonglong2 w[C];
#pragma unroll
            for (int j = 0; j < C; ++j) w[j] = wp[j][g];
#pragma unroll
            for (int i = 0; i < R; ++i) {
                ulonglong2 a = xp[i][g];   // broadcast within warp
#pragma unroll
                for (int j = 0; j < C; ++j) {
                    FMA2(acc[i][j], a.x, w[j].x);
                    FMA2(acc[i][j], a.y, w[j].y);
                }
            }
        }

        // unpack + bias
        float val[R][C];
#pragma unroll
        for (int i = 0; i < R; ++i)
#pragma unroll
            for (int j = 0; j < C; ++j) {
                float lo, hi;
                UNPACK2(lo, hi, acc[i][j]);
                val[i][j] = lo + hi + breg[j];
            }

        if (RELU) {
#pragma unroll
            for (int i = 0; i < R; ++i) {
                int gr = row0 + ty + 4 * i;
                if (gr < M) {
#pragma unroll
                    for (int j = 0; j < C; ++j)
                        Y[(size_t)gr * N + tx + 64 * j] = fmaxf(val[i][j], 0.f);
                }
            }
        } else {   // L2N, N==128, C==2
            // per-warp partial sum of squares per row, then combine warp pair
            float ssq[R];
#pragma unroll
            for (int i = 0; i < R; ++i) {
                float s = val[i][0] * val[i][0] + val[i][1] * val[i][1];
#pragma unroll
                for (int o = 16; o > 0; o >>= 1)
                    s += __shfl_xor_sync(0xffffffffu, s, o);
                ssq[i] = s;
            }
            if (lane == 0) {
#pragma unroll
                for (int i = 0; i < R; ++i) Sr[warp * R + i] = ssq[i];
            }
            __syncthreads();
#pragma unroll
            for (int i = 0; i < R; ++i) {
                float tot = Sr[warp * R + i] + Sr[(warp ^ 1) * R + i];
                float scale = 1.0f / fmaxf(sqrtf(tot), 1e-12f);
                int gr = row0 + ty + 4 * i;
                if (gr < M) {
                    Y[(size_t)gr * 128 + tx]      = val[i][0] * scale;
                    Y[(size_t)gr * 128 + tx + 64] = val[i][1] * scale;
                }
            }
        }
    }
}

// ---------------------------------------------------------------------------
// Segment boundaries from sorted seg_ids (users with no interactions -> [0,0))
// ---------------------------------------------------------------------------
__global__ void bounds_init_kernel(int* __restrict__ s, int* __restrict__ e, int n)
{
    int i = blockIdx.x * blockDim.x + threadIdx.x;
    if (i < n) { s[i] = 0; e[i] = 0; }
}

__global__ void bounds_kernel(const int* __restrict__ seg, int n,
                              int* __restrict__ s, int* __restrict__ e)
{
    int i = blockIdx.x * blockDim.x + threadIdx.x;
    if (i >= n) return;
    int id = seg[i];
    if (i == 0 || seg[i - 1] != id) s[id] = i;
    if (i == n - 1 || seg[i + 1] != id) e[id] = i + 1;
}

// ---------------------------------------------------------------------------
// One warp per user: fused[u] = concat(gcn_user_emb[users[u]], mean(item_emb))
// ---------------------------------------------------------------------------
__global__ void hist_kernel(const float* __restrict__ item_emb,
                            const int* __restrict__ item_idx,
                            const int* __restrict__ sa,
                            const int* __restrict__ ea,
                            const float* __restrict__ gue,
                            const int* __restrict__ users,
                            float* __restrict__ fused, int n_users)
{
    int w = (blockIdx.x * blockDim.x + threadIdx.x) >> 5;
    int lane = threadIdx.x & 31;
    if (w >= n_users) return;

    int uu = users[w];

    if (lane < 16) {
        float4 g = reinterpret_cast<const float4*>(gue + (size_t)uu * GCN)[lane];
        reinterpret_cast<float4*>(fused + (size_t)w * (GCN + TOW))[lane] = g;
    }

    int s = sa[uu], e = ea[uu];
    const float4* emb4 = reinterpret_cast<const float4*>(item_emb);

    float4 acc = make_float4(0.f, 0.f, 0.f, 0.f);
    int j = s;
    for (; j + 4 <= e; j += 4) {
        int i0 = item_idx[j], i1 = item_idx[j + 1], i2 = item_idx[j + 2], i3 = item_idx[j + 3];
        float4 v0 = emb4[(size_t)i0 * 32 + lane];
        float4 v1 = emb4[(size_t)i1 * 32 + lane];
        float4 v2 = emb4[(size_t)i2 * 32 + lane];
        float4 v3 = emb4[(size_t)i3 * 32 + lane];
        acc.x += (v0.x + v1.x) + (v2.x + v3.x);
        acc.y += (v0.y + v1.y) + (v2.y + v3.y);
        acc.z += (v0.z + v1.z) + (v2.z + v3.z);
        acc.w += (v0.w + v1.w) + (v2.w + v3.w);
    }
    for (; j < e; ++j) {
        int it = item_idx[j];
        float4 v = emb4[(size_t)it * 32 + lane];
        acc.x += v.x; acc.y += v.y; acc.z += v.z; acc.w += v.w;
    }
    float inv = 1.0f / fmaxf((float)(e - s), 1.0f);
    float4 m = make_float4(acc.x * inv, acc.y * inv, acc.z * inv, acc.w * inv);
    reinterpret_cast<float4*>(fused + (size_t)w * (GCN + TOW) + GCN)[lane] = m;
}

// ---------------------------------------------------------------------------
extern "C" void kernel_launch(void* const* d_in, const int* in_sizes, int n_in,
                              void* d_out, int out_size)
{
    const float* item_feat    = (const float*)d_in[0];
    const float* gcn_item_emb = (const float*)d_in[1];
    const float* gcn_user_emb = (const float*)d_in[2];
    const float* Wi1 = (const float*)d_in[3];
    const float* bi1 = (const float*)d_in[4];
    const float* Wi2 = (const float*)d_in[5];
    const float* bi2 = (const float*)d_in[6];
    const float* Wu1 = (const float*)d_in[7];
    const float* bu1 = (const float*)d_in[8];
    const float* Wu2 = (const float*)d_in[9];
    const float* bu2 = (const float*)d_in[10];
    const int* item_idx = (const int*)d_in[11];
    const int* seg_ids  = (const int*)d_in[12];
    const int* users    = (const int*)d_in[13];
    float* out = (float*)d_out;

    float *item_emb, *H, *fused;
    int *st, *en;
    cudaGetSymbolAddress((void**)&item_emb, g_item_emb);
    cudaGetSymbolAddress((void**)&H, g_H);
    cudaGetSymbolAddress((void**)&fused, g_fused);
    cudaGetSymbolAddress((void**)&st, g_start);
    cudaGetSymbolAddress((void**)&en, g_end);

    // smem per instantiation: Ws[N*K4] + Xs[TR*K4] (+ Sr[8*R] for L2N)
    constexpr int K4_i1 = PadK<66>::value;    // 68
    constexpr int K4_l2 = PadK<256>::value;   // 260
    constexpr int K4_u1 = PadK<192>::value;   // 196
    const int smem_i1 = (256 * K4_i1 + 32 * K4_i1) * 4;                 // ~78 KB
    const int smem_l2 = (128 * K4_l2 + 64 * K4_l2 + 8 * 16) * 4;        // ~196 KB
    const int smem_u1 = (256 * K4_u1 + 32 * K4_u1) * 4;                 // ~226 KB

    cudaFuncSetAttribute((const void*)gemm_kernel<66, 256, true, false>,
                         cudaFuncAttributeMaxDynamicSharedMemorySize, smem_i1);
    cudaFuncSetAttribute((const void*)gemm_kernel<256, 128, false, true>,
                         cudaFuncAttributeMaxDynamicSharedMemorySize, smem_l2);
    cudaFuncSetAttribute((const void*)gemm_kernel<192, 256, true, false>,
                         cudaFuncAttributeMaxDynamicSharedMemorySize, smem_u1);

    const int GRID = 152;   // persistent, 1 CTA per SM

    // 1) item L1: H = relu(concat(item_feat, gcn_item_emb) @ Wi1 + bi1)
    gemm_kernel<66, 256, true, false><<<GRID, 256, smem_i1>>>(
        item_feat, 2, gcn_item_emb, Wi1, bi1, H, N_ITEMS);

    // 2) item L2 + L2 norm -> item_emb
    gemm_kernel<256, 128, false, true><<<GRID, 256, smem_l2>>>(
        H, 256, H, Wi2, bi2, item_emb, N_ITEMS);

    // 3) segment boundaries
    bounds_init_kernel<<<(N_USERS + 255) / 256, 256>>>(st, en, N_USERS);
    bounds_kernel<<<(N_INTER + 255) / 256, 256>>>(seg_ids, N_INTER, st, en);

    // 4) ragged gather + mean -> fused
    hist_kernel<<<(N_USERS * 32 + 255) / 256, 256>>>(
        item_emb, item_idx, st, en, gcn_user_emb, users, fused, N_USERS);

    // 5) user L1
    gemm_kernel<192, 256, true, false><<<GRID, 256, smem_u1>>>(
        fused, 192, fused, Wu1, bu1, H, N_USERS);

    // 6) user L2 + L2 norm -> output
    gemm_kernel<256, 128, false, true><<<GRID, 256, smem_l2>>>(
        H, 256, H, Wu2, bu2, out, N_USERS);
}

// round 3
// speedup vs baseline: 1.0746x; 1.0021x over previous
#include <cuda_runtime.h>
#include <math.h>

#define N_ITEMS 200000
#define N_USERS 100000
#define N_INTER 2000000
#define GCN 64
#define HID 256
#define TOW 128

typedef unsigned long long u64;

// packed dual-FMA: (d.lo,d.hi) += (a.lo*b.lo, a.hi*b.hi)
#define FMA2(d, a, b) \
    asm("fma.rn.f32x2 %0, %1, %2, %0;" : "+l"(d) : "l"(a), "l"(b))

#define UNPACK2(lo, hi, p) \
    asm("mov.b64 {%0, %1}, %2;" : "=f"(lo), "=f"(hi) : "l"(p))

// ---------------- scratch (static device globals; no runtime alloc) ----------
__device__ float g_item_emb[(size_t)N_ITEMS * TOW];      // 102.4 MB
__device__ float g_H[(size_t)N_ITEMS * HID];             // 204.8 MB (reused by user tower)
__device__ float g_fused[(size_t)N_USERS * (GCN + TOW)]; // 76.8 MB
__device__ int   g_start[N_USERS];
__device__ int   g_end[N_USERS];

// padded K stride: multiple of 4 words AND ≡4 (mod 8) so 8-lane LDS.128 phases
// are bank-conflict-free (stride*4 words per lane covers all 32 banks).
template <int K> struct PadK {
    static constexpr int a = (K + 3) & ~3;
    static constexpr int value = (a % 8 == 4) ? a : a + 4;
};

// ---------------------------------------------------------------------------
// Fused layer: Y = post( X @ W + b ),  X = concat(X1[:k1], X2[:K-k1])
//  - W transposed into SMEM as Wt[N][K4] once per CTA (persistent CTAs)
//  - 256 threads = 4 row-groups x 64 col-lanes
//  - per-thread register tile: R rows x C cols, accumulated as f32x2 packed
//    along k (k, k+1) -> both operands naturally packed from LDS.128
//  - RELU: bias+relu+store.  L2N (N==128): per-row cross-warp L2 normalize.
// ---------------------------------------------------------------------------
template <int K, int N, bool RELU, bool L2N>
__global__ void __launch_bounds__(256, 1)
gemm_kernel(const float* __restrict__ X1, int k1,
            const float* __restrict__ X2,
            const float* __restrict__ W,
            const float* __restrict__ bias,
            float* __restrict__ Y, int M)
{
    constexpr int K4 = PadK<K>::value;
    constexpr int C  = N / 64;             // cols per thread (2 or 4)
    constexpr int R  = 32 / C;             // rows per thread (16 or 8)
    constexpr int TR = 4 * R;              // tile rows (64 or 32)
    constexpr int NG = K4 / 4;             // 4-k groups

    extern __shared__ float sm[];
    float* Ws = sm;                        // [N][K4] transposed weights
    float* Xs = sm + (size_t)N * K4;       // [TR][K4]
    float* Sr = Xs + (size_t)TR * K4;      // [8][R] row ssq partials (L2N)

    const int tid = threadIdx.x;
    const int ty = tid >> 6;               // 0..3
    const int tx = tid & 63;               // 0..63
    const int warp = tid >> 5;
    const int lane = tid & 31;

    // Stage transposed weights once (strided global reads -> coalesced STS).
    for (int i = tid; i < N * K4; i += 256) {
        int n = i / K4, k = i - n * K4;
        Ws[i] = (k < K) ? W[k * N + n] : 0.f;
    }

    float breg[C];
#pragma unroll
    for (int j = 0; j < C; ++j) breg[j] = bias[tx + 64 * j];

    const ulonglong2* wp[C];
#pragma unroll
    for (int j = 0; j < C; ++j)
        wp[j] = reinterpret_cast<const ulonglong2*>(Ws + (size_t)(tx + 64 * j) * K4);
    const ulonglong2* xp[R];
#pragma unroll
    for (int i = 0; i < R; ++i)
        xp[i] = reinterpret_cast<const ulonglong2*>(Xs + (size_t)(ty + 4 * i) * K4);

    const int ntiles = (M + TR - 1) / TR;
    for (int tile = blockIdx.x; tile < ntiles; tile += gridDim.x) {
        const int row0 = tile * TR;
        __syncthreads();   // protect Xs/Sr from previous iteration (and W load, 1st)

        // Stage X tile [TR x K4] with concat, tail guard, zero pad.
        for (int i = tid; i < TR * K4; i += 256) {
            int r = i / K4, c = i - r * K4;
            int gr = row0 + r;
            float v = 0.f;
            if (gr < M && c < K)
                v = (c < k1) ? X1[(size_t)gr * k1 + c]
                             : X2[(size_t)gr * (K - k1) + (c - k1)];
            Xs[i] = v;
        }
        __syncthreads();

        u64 acc[R][C];
#pragma unroll
        for (int i = 0; i < R; ++i)
#pragma unroll
            for (int j = 0; j < C; ++j) acc[i][j] = 0ull;

#pragma unroll 2
        for (int g = 0; g < NG; ++g) {
            ulonglong2 w[C];
#pragma unroll
            for (int j = 0; j < C; ++j) w[j] = wp[j][g];
#pragma unroll
            for (int i = 0; i < R; ++i) {
                ulonglong2 a = xp[i][g];   // broadcast within warp
#pragma unroll
                for (int j = 0; j < C; ++j) {
                    FMA2(acc[i][j], a.x, w[j].x);
                    FMA2(acc[i][j], a.y, w[j].y);
                }
            }
        }

        // unpack + bias
        float val[R][C];
#pragma unroll
        for (int i = 0; i < R; ++i)
#pragma unroll
            for (int j = 0; j < C; ++j) {
                float lo, hi;
                UNPACK2(lo, hi, acc[i][j]);
                val[i][j] = lo + hi + breg[j];
            }

        if (RELU) {
#pragma unroll
            for (int i = 0; i < R; ++i) {
                int gr = row0 + ty + 4 * i;
                if (gr < M) {
#pragma unroll
                    for (int j = 0; j < C; ++j)
                        Y[(size_t)gr * N + tx + 64 * j] = fmaxf(val[i][j], 0.f);
                }
            }
        } else {   // L2N, N==128, C==2
            // per-warp partial sum of squares per row, then combine warp pair
            float ssq[R];
#pragma unroll
            for (int i = 0; i < R; ++i) {
                float s = val[i][0] * val[i][0] + val[i][1] * val[i][1];
#pragma unroll
                for (int o = 16; o > 0; o >>= 1)
                    s += __shfl_xor_sync(0xffffffffu, s, o);
                ssq[i] = s;
            }
            if (lane == 0) {
#pragma unroll
                for (int i = 0; i < R; ++i) Sr[warp * R + i] = ssq[i];
            }
            __syncthreads();
#pragma unroll
            for (int i = 0; i < R; ++i) {
                float tot = Sr[warp * R + i] + Sr[(warp ^ 1) * R + i];
                float scale = 1.0f / fmaxf(sqrtf(tot), 1e-12f);
                int gr = row0 + ty + 4 * i;
                if (gr < M) {
                    Y[(size_t)gr * 128 + tx]      = val[i][0] * scale;
                    Y[(size_t)gr * 128 + tx + 64] = val[i][1] * scale;
                }
            }
        }
    }
}

// ---------------------------------------------------------------------------
// Segment boundaries from sorted seg_ids (users with no interactions -> [0,0))
// ---------------------------------------------------------------------------
__global__ void bounds_init_kernel(int* __restrict__ s, int* __restrict__ e, int n)
{
    int i = blockIdx.x * blockDim.x + threadIdx.x;
    if (i < n) { s[i] = 0; e[i] = 0; }
}

__global__ void bounds_kernel(const int* __restrict__ seg, int n,
                              int* __restrict__ s, int* __restrict__ e)
{
    int i = blockIdx.x * blockDim.x + threadIdx.x;
    if (i >= n) return;
    int id = seg[i];
    if (i == 0 || seg[i - 1] != id) s[id] = i;
    if (i == n - 1 || seg[i + 1] != id) e[id] = i + 1;
}

// ---------------------------------------------------------------------------
// One warp per user: fused[u] = concat(gcn_user_emb[users[u]], mean(item_emb))
// ---------------------------------------------------------------------------
__global__ void hist_kernel(const float* __restrict__ item_emb,
                            const int* __restrict__ item_idx,
                            const int* __restrict__ sa,
                            const int* __restrict__ ea,
                            const float* __restrict__ gue,
                            const int* __restrict__ users,
                            float* __restrict__ fused, int n_users)
{
    int w = (blockIdx.x * blockDim.x + threadIdx.x) >> 5;
    int lane = threadIdx.x & 31;
    if (w >= n_users) return;

    int uu = users[w];

    if (lane < 16) {
        float4 g = reinterpret_cast<const float4*>(gue + (size_t)uu * GCN)[lane];
        reinterpret_cast<float4*>(fused + (size_t)w * (GCN + TOW))[lane] = g;
    }

    int s = sa[uu], e = ea[uu];
    const float4* emb4 = reinterpret_cast<const float4*>(item_emb);

    float4 acc = make_float4(0.f, 0.f, 0.f, 0.f);
    int j = s;
    for (; j + 4 <= e; j += 4) {
        int i0 = item_idx[j], i1 = item_idx[j + 1], i2 = item_idx[j + 2], i3 = item_idx[j + 3];
        float4 v0 = emb4[(size_t)i0 * 32 + lane];
        float4 v1 = emb4[(size_t)i1 * 32 + lane];
        float4 v2 = emb4[(size_t)i2 * 32 + lane];
        float4 v3 = emb4[(size_t)i3 * 32 + lane];
        acc.x += (v0.x + v1.x) + (v2.x + v3.x);
        acc.y += (v0.y + v1.y) + (v2.y + v3.y);
        acc.z += (v0.z + v1.z) + (v2.z + v3.z);
        acc.w += (v0.w + v1.w) + (v2.w + v3.w);
    }
    for (; j < e; ++j) {
        int it = item_idx[j];
        float4 v = emb4[(size_t)it * 32 + lane];
        acc.x += v.x; acc.y += v.y; acc.z += v.z; acc.w += v.w;
    }
    float inv = 1.0f / fmaxf((float)(e - s), 1.0f);
    float4 m = make_float4(acc.x * inv, acc.y * inv, acc.z * inv, acc.w * inv);
    reinterpret_cast<float4*>(fused + (size_t)w * (GCN + TOW) + GCN)[lane] = m;
}

// ---------------------------------------------------------------------------
extern "C" void kernel_launch(void* const* d_in, const int* in_sizes, int n_in,
                              void* d_out, int out_size)
{
    const float* item_feat    = (const float*)d_in[0];
    const float* gcn_item_emb = (const float*)d_in[1];
    const float* gcn_user_emb = (const float*)d_in[2];
    const float* Wi1 = (const float*)d_in[3];
    const float* bi1 = (const float*)d_in[4];
    const float* Wi2 = (const float*)d_in[5];
    const float* bi2 = (const float*)d_in[6];
    const float* Wu1 = (const float*)d_in[7];
    const float* bu1 = (const float*)d_in[8];
    const float* Wu2 = (const float*)d_in[9];
    const float* bu2 = (const float*)d_in[10];
    const int* item_idx = (const int*)d_in[11];
    const int* seg_ids  = (const int*)d_in[12];
    const int* users    = (const int*)d_in[13];
    float* out = (float*)d_out;

    float *item_emb, *H, *fused;
    int *st, *en;
    cudaGetSymbolAddress((void**)&item_emb, g_item_emb);
    cudaGetSymbolAddress((void**)&H, g_H);
    cudaGetSymbolAddress((void**)&fused, g_fused);
    cudaGetSymbolAddress((void**)&st, g_start);
    cudaGetSymbolAddress((void**)&en, g_end);

    // smem per instantiation: Ws[N*K4] + Xs[TR*K4] (+ Sr[8*R] for L2N)
    constexpr int K4_i1 = PadK<66>::value;    // 68
    constexpr int K4_l2 = PadK<256>::value;   // 260
    constexpr int K4_u1 = PadK<192>::value;   // 196
    const int smem_i1 = (256 * K4_i1 + 32 * K4_i1) * 4;                 // ~78 KB
    const int smem_l2 = (128 * K4_l2 + 64 * K4_l2 + 8 * 16) * 4;        // ~196 KB
    const int smem_u1 = (256 * K4_u1 + 32 * K4_u1) * 4;                 // ~226 KB

    cudaFuncSetAttribute((const void*)gemm_kernel<66, 256, true, false>,
                         cudaFuncAttributeMaxDynamicSharedMemorySize, smem_i1);
    cudaFuncSetAttribute((const void*)gemm_kernel<256, 128, false, true>,
                         cudaFuncAttributeMaxDynamicSharedMemorySize, smem_l2);
    cudaFuncSetAttribute((const void*)gemm_kernel<192, 256, true, false>,
                         cudaFuncAttributeMaxDynamicSharedMemorySize, smem_u1);

    const int GRID = 152;   // persistent, 1 CTA per SM

    // 1) item L1: H = relu(concat(item_feat, gcn_item_emb) @ Wi1 + bi1)
    gemm_kernel<66, 256, true, false><<<GRID, 256, smem_i1>>>(
        item_feat, 2, gcn_item_emb, Wi1, bi1, H, N_ITEMS);

    // 2) item L2 + L2 norm -> item_emb
    gemm_kernel<256, 128, false, true><<<GRID, 256, smem_l2>>>(
        H, 256, H, Wi2, bi2, item_emb, N_ITEMS);

    // 3) segment boundaries
    bounds_init_kernel<<<(N_USERS + 255) / 256, 256>>>(st, en, N_USERS);
    bounds_kernel<<<(N_INTER + 255) / 256, 256>>>(seg_ids, N_INTER, st, en);

    // 4) ragged gather + mean -> fused
    hist_kernel<<<(N_USERS * 32 + 255) / 256, 256>>>(
        item_emb, item_idx, st, en, gcn_user_emb, users, fused, N_USERS);

    // 5) user L1
    gemm_kernel<192, 256, true, false><<<GRID, 256, smem_u1>>>(
        fused, 192, fused, Wu1, bu1, H, N_USERS);

    // 6) user L2 + L2 norm -> output
    gemm_kernel<256, 128, false, true><<<GRID, 256, smem_l2>>>(
        H, 256, H, Wu2, bu2, out, N_USERS);
}